// round 4
// baseline (speedup 1.0000x reference)
#include <cuda_runtime.h>
#include <math.h>

#define F 39
#define E 16
#define A 16
#define NPAIR 741            // F*(F-1)/2
#define THREADS 256
#define EMB_STRIDE 17        // pad to kill bank conflicts on scattered row reads

__global__ __launch_bounds__(THREADS, 2) void afm_kernel(
    const int*   __restrict__ feat_index,   // [B,F]
    const float* __restrict__ feat_value,   // [B,F]
    const float* __restrict__ fow,          // [V,1]
    const float* __restrict__ emb_table,    // [V,E]
    const float* __restrict__ bias,         // [1]
    const float* __restrict__ att_w,        // [E,A] row-major
    const float* __restrict__ att_b,        // [A]
    const float* __restrict__ proj_h,       // [A,1]
    const float* __restrict__ proj_p,       // [E,1]
    float*       __restrict__ out)          // [B]
{
    __shared__ float  s_emb[F * EMB_STRIDE];
    __shared__ float4 s_W[E * 4];           // W[e][a]: 4 float4 per e-row
    __shared__ float  s_ab[A];
    __shared__ float  s_h[A];
    __shared__ float  s_pp[E];
    __shared__ float  s_score[NPAIR];
    __shared__ unsigned char s_pi[NPAIR];
    __shared__ unsigned char s_pj[NPAIR];
    __shared__ float  s_red[32];
    __shared__ float  s_pool[16][17];       // [group][e], padded
    __shared__ float  s_scalar[4];          // 0: y_first, 1: max, 2: Z
    __shared__ int    s_idx[F];
    __shared__ float  s_val[F];

    const int b    = blockIdx.x;
    const int tid  = threadIdx.x;
    const int lane = tid & 31;
    const int wid  = tid >> 5;

    // ---------------- Phase A: loads ----------------
    if (tid == 0) s_scalar[0] = 0.0f;
    if (tid < F) {
        s_idx[tid] = feat_index[b * F + tid];
        s_val[tid] = feat_value[b * F + tid];
    }
    // pair index tables (independent of data)
    for (int p = tid; p < NPAIR; p += THREADS) {
        int i = (int)floorf((77.0f - sqrtf(5929.0f - 8.0f * (float)p)) * 0.5f);
        if (i < 0) i = 0;
        if (i > F - 2) i = F - 2;
        while (i < F - 2 && (77 * (i + 1) - (i + 1) * (i + 1)) / 2 <= p) ++i;
        while (i > 0 && (77 * i - i * i) / 2 > p) --i;
        int base = (77 * i - i * i) / 2;
        s_pi[p] = (unsigned char)i;
        s_pj[p] = (unsigned char)(i + 1 + (p - base));
    }
    if (tid < E * A / 4) s_W[tid] = ((const float4*)att_w)[tid];
    if (tid < A)  s_ab[tid] = att_b[tid];
    if (tid < A)  s_h[tid]  = proj_h[tid];
    if (tid < E)  s_pp[tid] = proj_p[tid];
    __syncthreads();

    // scaled embedding gather
    for (int t = tid; t < F * E; t += THREADS) {
        int f = t >> 4, e = t & 15;
        s_emb[f * EMB_STRIDE + e] = emb_table[s_idx[f] * E + e] * s_val[f];
    }
    // first-order term
    if (tid < F) {
        atomicAdd(&s_scalar[0], fow[s_idx[tid]] * s_val[tid]);
    }
    __syncthreads();

    // ---------------- Phase B: pair scores ----------------
    for (int p = tid; p < NPAIR; p += THREADS) {
        const int i = s_pi[p];
        const int j = s_pj[p];
        const float* ei = &s_emb[i * EMB_STRIDE];
        const float* ej = &s_emb[j * EMB_STRIDE];

        float att[16];
        #pragma unroll
        for (int a = 0; a < 16; ++a) att[a] = s_ab[a];

        #pragma unroll
        for (int e = 0; e < 16; ++e) {
            float  be = ei[e] * ej[e];
            float4 w0 = s_W[e * 4 + 0];
            float4 w1 = s_W[e * 4 + 1];
            float4 w2 = s_W[e * 4 + 2];
            float4 w3 = s_W[e * 4 + 3];
            att[0]  = fmaf(be, w0.x, att[0]);
            att[1]  = fmaf(be, w0.y, att[1]);
            att[2]  = fmaf(be, w0.z, att[2]);
            att[3]  = fmaf(be, w0.w, att[3]);
            att[4]  = fmaf(be, w1.x, att[4]);
            att[5]  = fmaf(be, w1.y, att[5]);
            att[6]  = fmaf(be, w1.z, att[6]);
            att[7]  = fmaf(be, w1.w, att[7]);
            att[8]  = fmaf(be, w2.x, att[8]);
            att[9]  = fmaf(be, w2.y, att[9]);
            att[10] = fmaf(be, w2.z, att[10]);
            att[11] = fmaf(be, w2.w, att[11]);
            att[12] = fmaf(be, w3.x, att[12]);
            att[13] = fmaf(be, w3.y, att[13]);
            att[14] = fmaf(be, w3.z, att[14]);
            att[15] = fmaf(be, w3.w, att[15]);
        }

        float sc = 0.0f;
        #pragma unroll
        for (int a = 0; a < 16; ++a)
            sc = fmaf(fmaxf(att[a], 0.0f), s_h[a], sc);
        s_score[p] = sc;
    }
    __syncthreads();

    // ---------------- Phase C: softmax over pairs ----------------
    float m = -1e30f;
    for (int p = tid; p < NPAIR; p += THREADS) m = fmaxf(m, s_score[p]);
    #pragma unroll
    for (int o = 16; o > 0; o >>= 1) m = fmaxf(m, __shfl_xor_sync(0xFFFFFFFFu, m, o));
    if (lane == 0) s_red[wid] = m;
    __syncthreads();
    if (tid == 0) {
        float mm = s_red[0];
        #pragma unroll
        for (int w = 1; w < THREADS / 32; ++w) mm = fmaxf(mm, s_red[w]);
        s_scalar[1] = mm;
    }
    __syncthreads();

    const float M = s_scalar[1];
    float zs = 0.0f;
    for (int p = tid; p < NPAIR; p += THREADS) {
        float ev = __expf(s_score[p] - M);
        s_score[p] = ev;
        zs += ev;
    }
    #pragma unroll
    for (int o = 16; o > 0; o >>= 1) zs += __shfl_xor_sync(0xFFFFFFFFu, zs, o);
    if (lane == 0) s_red[wid] = zs;
    __syncthreads();
    if (tid == 0) {
        float z = 0.0f;
        #pragma unroll
        for (int w = 0; w < THREADS / 32; ++w) z += s_red[w];
        s_scalar[2] = z;
    }
    __syncthreads();

    // ---------------- Phase D: weighted pooled sum ----------------
    {
        int e = tid & 15;
        int g = tid >> 4;          // 16 groups of pairs
        float acc = 0.0f;
        for (int p = g; p < NPAIR; p += 16) {
            int i = s_pi[p], j = s_pj[p];
            acc = fmaf(s_score[p],
                       s_emb[i * EMB_STRIDE + e] * s_emb[j * EMB_STRIDE + e],
                       acc);
        }
        s_pool[g][e] = acc;
    }
    __syncthreads();

    if (tid < E) {
        float pe = 0.0f;
        #pragma unroll
        for (int g = 0; g < 16; ++g) pe += s_pool[g][tid];
        s_red[tid] = pe * s_pp[tid];
    }
    __syncthreads();

    if (tid == 0) {
        float aw = 0.0f;
        #pragma unroll
        for (int e = 0; e < E; ++e) aw += s_red[e];
        float y = bias[0] + s_scalar[0] + aw / s_scalar[2];
        out[b] = 1.0f / (1.0f + expf(-y));
    }
}

extern "C" void kernel_launch(void* const* d_in, const int* in_sizes, int n_in,
                              void* d_out, int out_size) {
    const int*   feat_index = (const int*)  d_in[0];
    const float* feat_value = (const float*)d_in[1];
    const float* fow        = (const float*)d_in[2];
    const float* emb_table  = (const float*)d_in[3];
    const float* bias       = (const float*)d_in[4];
    const float* att_w      = (const float*)d_in[5];
    const float* att_b      = (const float*)d_in[6];
    const float* proj_h     = (const float*)d_in[7];
    const float* proj_p     = (const float*)d_in[8];
    float* out = (float*)d_out;

    int nb = in_sizes[0] / F;   // batch rows
    afm_kernel<<<nb, THREADS>>>(feat_index, feat_value, fow, emb_table, bias,
                                att_w, att_b, proj_h, proj_p, out);
}

// round 9
// speedup vs baseline: 1.6720x; 1.6720x over previous
#include <cuda_runtime.h>
#include <math.h>

#define F 39
#define E 16
#define A 16
#define NPAIR 741            // F*(F-1)/2
#define ESTR 17              // padded emb row stride (odd -> conflict-free)
#define WARPS 8
#define THREADS 256

// packed fp32x2 FMA (sm_100+; ptxas only emits FFMA2 via this PTX form)
#define FMA2(d, a, b, c) \
    asm("fma.rn.f32x2 %0, %1, %2, %3;" : "=l"(d) : "l"(a), "l"(b), "l"(c))

__global__ __launch_bounds__(THREADS, 2) void afm_kernel(
    const int*   __restrict__ feat_index,   // [B,F]
    const float* __restrict__ feat_value,   // [B,F]
    const float* __restrict__ fow,          // [V,1]
    const float* __restrict__ emb_table,    // [V,E]
    const float* __restrict__ bias,         // [1]
    const float* __restrict__ att_w,        // [E,A] row-major
    const float* __restrict__ att_b,        // [A]
    const float* __restrict__ proj_h,       // [A,1]
    const float* __restrict__ proj_p,       // [E,1]
    float*       __restrict__ out,          // [B]
    int nb)
{
    __shared__ float s_emb[WARPS][F * ESTR];      // 21216 B
    __shared__ float s_score[WARPS][NPAIR];       // 23712 B
    __shared__ __align__(16) float s_W[E * A];    // 1024 B
    __shared__ __align__(16) float s_ab[A];
    __shared__ float s_h[A];
    __shared__ float s_pp[E];
    __shared__ unsigned short s_pij[NPAIR];       // i | (j<<8)

    const int tid  = threadIdx.x;
    const int lane = tid & 31;
    const int wid  = tid >> 5;

    // ---- one-time CTA-wide tables (row-independent) ----
    for (int p = tid; p < NPAIR; p += THREADS) {
        int i = (int)floorf((77.0f - sqrtf(5929.0f - 8.0f * (float)p)) * 0.5f);
        if (i < 0) i = 0;
        if (i > F - 2) i = F - 2;
        while (i < F - 2 && (77 * (i + 1) - (i + 1) * (i + 1)) / 2 <= p) ++i;
        while (i > 0 && (77 * i - i * i) / 2 > p) --i;
        int j = i + 1 + (p - (77 * i - i * i) / 2);
        s_pij[p] = (unsigned short)(i | (j << 8));
    }
    if (tid < E * A / 4) ((float4*)s_W)[tid] = ((const float4*)att_w)[tid];
    if (tid < A) { s_ab[tid] = att_b[tid]; s_h[tid] = proj_h[tid]; s_pp[tid] = proj_p[tid]; }
    __syncthreads();   // the ONLY block-wide barrier

    const int row = blockIdx.x * WARPS + wid;
    if (row >= nb) return;

    float* emb   = s_emb[wid];
    float* score = s_score[wid];
    // temp aliases inside this warp's score region (dead before scores are written)
    int*   t_idx = (int*)score;          // [0,39)
    float* t_val = score + 64;           // [64,103)

    // ---- Phase A: indices, values, first-order, gather ----
    t_idx[lane] = feat_index[row * F + lane];
    t_val[lane] = feat_value[row * F + lane];
    if (lane < F - 32) {
        t_idx[32 + lane] = feat_index[row * F + 32 + lane];
        t_val[32 + lane] = feat_value[row * F + 32 + lane];
    }
    __syncwarp();

    float fo = t_val[lane] * fow[t_idx[lane]];
    if (lane < F - 32) fo += t_val[32 + lane] * fow[t_idx[32 + lane]];

    for (int t = lane; t < F * E; t += 32) {
        int f = t >> 4, e = t & 15;
        emb[f * ESTR + e] = emb_table[t_idx[f] * E + e] * t_val[f];
    }
    __syncwarp();   // all temp reads done; emb visible

    #pragma unroll
    for (int o = 16; o > 0; o >>= 1) fo += __shfl_xor_sync(~0u, fo, o);

    // ---- Phase B: pair scores (packed f32x2 MLP) ----
    float mloc = -1e30f;
    #pragma unroll 1
    for (int it = 0; it < 24; ++it) {
        int  p   = it * 32 + lane;
        bool act = p < NPAIR;
        int  v   = s_pij[act ? p : 0];
        const float* ei = emb + (v & 255) * ESTR;
        const float* ej = emb + (v >> 8) * ESTR;

        unsigned long long att[8];
        #pragma unroll
        for (int k = 0; k < 8; ++k)
            att[k] = ((const unsigned long long*)s_ab)[k];

        #pragma unroll
        for (int e = 0; e < 16; ++e) {
            float be = ei[e] * ej[e];
            unsigned long long be2;
            asm("mov.b64 %0, {%1, %1};" : "=l"(be2) : "f"(be));
            const ulonglong2* w = (const ulonglong2*)(s_W + e * A);
            ulonglong2 w0 = w[0], w1 = w[1], w2 = w[2], w3 = w[3];
            FMA2(att[0], be2, w0.x, att[0]);
            FMA2(att[1], be2, w0.y, att[1]);
            FMA2(att[2], be2, w1.x, att[2]);
            FMA2(att[3], be2, w1.y, att[3]);
            FMA2(att[4], be2, w2.x, att[4]);
            FMA2(att[5], be2, w2.y, att[5]);
            FMA2(att[6], be2, w3.x, att[6]);
            FMA2(att[7], be2, w3.y, att[7]);
        }

        float sc = 0.0f;
        #pragma unroll
        for (int k = 0; k < 8; ++k) {
            float lo, hi;
            asm("mov.b64 {%0, %1}, %2;" : "=f"(lo), "=f"(hi) : "l"(att[k]));
            sc = fmaf(fmaxf(lo, 0.0f), s_h[2 * k],     sc);
            sc = fmaf(fmaxf(hi, 0.0f), s_h[2 * k + 1], sc);
        }
        if (act) { score[p] = sc; mloc = fmaxf(mloc, sc); }
    }

    // ---- Phase C: warp softmax over 741 pairs ----
    #pragma unroll
    for (int o = 16; o > 0; o >>= 1) mloc = fmaxf(mloc, __shfl_xor_sync(~0u, mloc, o));

    float z = 0.0f;
    #pragma unroll 1
    for (int it = 0; it < 24; ++it) {
        int p = it * 32 + lane;
        if (p < NPAIR) {
            float ev = __expf(score[p] - mloc);
            score[p] = ev;
            z += ev;
        }
    }
    __syncwarp();
    #pragma unroll
    for (int o = 16; o > 0; o >>= 1) z += __shfl_xor_sync(~0u, z, o);

    // ---- Phase D: weighted pooled sum, projection, sigmoid ----
    {
        const int e = lane & 15;
        const int g = lane >> 4;     // 2 pair-groups
        float acc = 0.0f;
        #pragma unroll 2
        for (int p = g; p < NPAIR; p += 2) {
            int v = s_pij[p];
            acc = fmaf(score[p],
                       emb[(v & 255) * ESTR + e] * emb[(v >> 8) * ESTR + e],
                       acc);
        }
        acc += __shfl_xor_sync(~0u, acc, 16);
        float aw = acc * s_pp[e];
        #pragma unroll
        for (int o = 8; o > 0; o >>= 1) aw += __shfl_xor_sync(~0u, aw, o);

        if (lane == 0) {
            float y = bias[0] + fo + aw / z;
            out[row] = 1.0f / (1.0f + __expf(-y));
        }
    }
}

extern "C" void kernel_launch(void* const* d_in, const int* in_sizes, int n_in,
                              void* d_out, int out_size) {
    const int*   feat_index = (const int*)  d_in[0];
    const float* feat_value = (const float*)d_in[1];
    const float* fow        = (const float*)d_in[2];
    const float* emb_table  = (const float*)d_in[3];
    const float* bias       = (const float*)d_in[4];
    const float* att_w      = (const float*)d_in[5];
    const float* att_b      = (const float*)d_in[6];
    const float* proj_h     = (const float*)d_in[7];
    const float* proj_p     = (const float*)d_in[8];
    float* out = (float*)d_out;

    int nb = in_sizes[0] / F;   // batch rows
    int blocks = (nb + WARPS - 1) / WARPS;
    afm_kernel<<<blocks, THREADS>>>(feat_index, feat_value, fow, emb_table, bias,
                                    att_w, att_b, proj_h, proj_p, out, nb);
}

// round 10
// speedup vs baseline: 7.1215x; 4.2594x over previous
#include <cuda_runtime.h>
#include <math.h>

#define F 39
#define E 16
#define A 16
#define NPAIR 741            // F*(F-1)/2
#define ESTR 17              // padded emb row stride (odd -> conflict-free)
#define WARPS 8
#define THREADS 256

// MLP constants: warp-uniform, compile-time offsets -> uniform const-port
// loads (LDCU) on sm_103a, completely off the smem crossbar.
__constant__ __align__(16) float c_W[E * A];
__constant__ __align__(16) float c_ab[A];
__constant__ __align__(16) float c_h[A];
__constant__ __align__(16) float c_pp[E];

// packed fp32x2 FMA (sm_100+; ptxas only emits FFMA2 via this PTX form)
#define FMA2(d, a, b, c) \
    asm("fma.rn.f32x2 %0, %1, %2, %3;" : "=l"(d) : "l"(a), "l"(b), "l"(c))

__global__ __launch_bounds__(THREADS, 2) void afm_kernel(
    const int*   __restrict__ feat_index,   // [B,F]
    const float* __restrict__ feat_value,   // [B,F]
    const float* __restrict__ fow,          // [V,1]
    const float* __restrict__ emb_table,    // [V,E]
    const float* __restrict__ bias,         // [1]
    float*       __restrict__ out,          // [B]
    int nb)
{
    __shared__ float s_emb[WARPS][F * ESTR];      // 21216 B
    __shared__ float s_score[WARPS][NPAIR];       // 23712 B
    __shared__ unsigned short s_pij[NPAIR];       // i | (j<<8)

    const int tid  = threadIdx.x;
    const int lane = tid & 31;
    const int wid  = tid >> 5;

    // ---- one-time CTA-wide pair table (row-independent) ----
    for (int p = tid; p < NPAIR; p += THREADS) {
        int i = (int)floorf((77.0f - sqrtf(5929.0f - 8.0f * (float)p)) * 0.5f);
        if (i < 0) i = 0;
        if (i > F - 2) i = F - 2;
        while (i < F - 2 && (77 * (i + 1) - (i + 1) * (i + 1)) / 2 <= p) ++i;
        while (i > 0 && (77 * i - i * i) / 2 > p) --i;
        int j = i + 1 + (p - (77 * i - i * i) / 2);
        s_pij[p] = (unsigned short)(i | (j << 8));
    }
    __syncthreads();   // the ONLY block-wide barrier

    const int row = blockIdx.x * WARPS + wid;
    if (row >= nb) return;

    float* emb   = s_emb[wid];
    float* score = s_score[wid];
    // temp aliases inside this warp's score region (dead before scores are written)
    int*   t_idx = (int*)score;          // [0,39)
    float* t_val = score + 64;           // [64,103)

    // ---- Phase A: indices, values, first-order, gather ----
    t_idx[lane] = feat_index[row * F + lane];
    t_val[lane] = feat_value[row * F + lane];
    if (lane < F - 32) {
        t_idx[32 + lane] = feat_index[row * F + 32 + lane];
        t_val[32 + lane] = feat_value[row * F + 32 + lane];
    }
    __syncwarp();

    float fo = t_val[lane] * fow[t_idx[lane]];
    if (lane < F - 32) fo += t_val[32 + lane] * fow[t_idx[32 + lane]];

    for (int t = lane; t < F * E; t += 32) {
        int f = t >> 4, e = t & 15;
        emb[f * ESTR + e] = emb_table[t_idx[f] * E + e] * t_val[f];
    }
    __syncwarp();   // all temp reads done; emb visible

    #pragma unroll
    for (int o = 16; o > 0; o >>= 1) fo += __shfl_xor_sync(~0u, fo, o);

    // ---- Phase B: pair scores (packed f32x2 MLP, W from const port) ----
    float mloc = -1e30f;
    #pragma unroll 1
    for (int it = 0; it < 24; ++it) {
        int  p   = it * 32 + lane;
        bool act = p < NPAIR;
        int  v   = s_pij[act ? p : 0];
        const float* ei = emb + (v & 255) * ESTR;
        const float* ej = emb + (v >> 8) * ESTR;

        unsigned long long att[8];
        #pragma unroll
        for (int k = 0; k < 8; ++k)
            att[k] = ((const unsigned long long*)c_ab)[k];

        #pragma unroll
        for (int e = 0; e < 16; ++e) {
            float be = ei[e] * ej[e];
            unsigned long long be2;
            asm("mov.b64 %0, {%1, %1};" : "=l"(be2) : "f"(be));
            const unsigned long long* w = (const unsigned long long*)(c_W + e * A);
            FMA2(att[0], be2, w[0], att[0]);
            FMA2(att[1], be2, w[1], att[1]);
            FMA2(att[2], be2, w[2], att[2]);
            FMA2(att[3], be2, w[3], att[3]);
            FMA2(att[4], be2, w[4], att[4]);
            FMA2(att[5], be2, w[5], att[5]);
            FMA2(att[6], be2, w[6], att[6]);
            FMA2(att[7], be2, w[7], att[7]);
        }

        float sc = 0.0f;
        #pragma unroll
        for (int k = 0; k < 8; ++k) {
            float lo, hi;
            asm("mov.b64 {%0, %1}, %2;" : "=f"(lo), "=f"(hi) : "l"(att[k]));
            sc = fmaf(fmaxf(lo, 0.0f), c_h[2 * k],     sc);
            sc = fmaf(fmaxf(hi, 0.0f), c_h[2 * k + 1], sc);
        }
        if (act) { score[p] = sc; mloc = fmaxf(mloc, sc); }
    }

    // ---- Phase C: warp softmax over 741 pairs ----
    #pragma unroll
    for (int o = 16; o > 0; o >>= 1) mloc = fmaxf(mloc, __shfl_xor_sync(~0u, mloc, o));

    float z = 0.0f;
    #pragma unroll 1
    for (int it = 0; it < 24; ++it) {
        int p = it * 32 + lane;
        if (p < NPAIR) {
            float ev = __expf(score[p] - mloc);
            score[p] = ev;
            z += ev;
        }
    }
    __syncwarp();
    #pragma unroll
    for (int o = 16; o > 0; o >>= 1) z += __shfl_xor_sync(~0u, z, o);

    // ---- Phase D: weighted pooled sum, projection, sigmoid ----
    {
        const int e = lane & 15;
        const int g = lane >> 4;     // 2 pair-groups
        float acc = 0.0f;
        #pragma unroll 2
        for (int p = g; p < NPAIR; p += 2) {
            int v = s_pij[p];
            acc = fmaf(score[p],
                       emb[(v & 255) * ESTR + e] * emb[(v >> 8) * ESTR + e],
                       acc);
        }
        acc += __shfl_xor_sync(~0u, acc, 16);
        float aw = acc * c_pp[e];
        #pragma unroll
        for (int o = 8; o > 0; o >>= 1) aw += __shfl_xor_sync(~0u, aw, o);

        if (lane == 0) {
            float y = bias[0] + fo + aw / z;
            out[row] = 1.0f / (1.0f + __expf(-y));
        }
    }
}

extern "C" void kernel_launch(void* const* d_in, const int* in_sizes, int n_in,
                              void* d_out, int out_size) {
    const int*   feat_index = (const int*)  d_in[0];
    const float* feat_value = (const float*)d_in[1];
    const float* fow        = (const float*)d_in[2];
    const float* emb_table  = (const float*)d_in[3];
    const float* bias       = (const float*)d_in[4];
    float* out = (float*)d_out;

    // Stage the tiny MLP weights into constant memory (graph-capturable
    // device-to-device async copies on the capture stream; no allocation).
    cudaMemcpyToSymbolAsync(c_W,  d_in[5], E * A * sizeof(float), 0, cudaMemcpyDeviceToDevice);
    cudaMemcpyToSymbolAsync(c_ab, d_in[6], A * sizeof(float),     0, cudaMemcpyDeviceToDevice);
    cudaMemcpyToSymbolAsync(c_h,  d_in[7], A * sizeof(float),     0, cudaMemcpyDeviceToDevice);
    cudaMemcpyToSymbolAsync(c_pp, d_in[8], E * sizeof(float),     0, cudaMemcpyDeviceToDevice);

    int nb = in_sizes[0] / F;   // batch rows
    int blocks = (nb + WARPS - 1) / WARPS;
    afm_kernel<<<blocks, THREADS>>>(feat_index, feat_value, fow, emb_table, bias,
                                    out, nb);
}

// round 11
// speedup vs baseline: 7.7415x; 1.0871x over previous
#include <cuda_runtime.h>
#include <math.h>

#define F 39
#define E 16
#define A 16
#define NPAIR 741            // F*(F-1)/2
#define ESTR 20              // emb row stride: 80 B = odd # of 16B units -> float4-clean
#define WARPS 8
#define THREADS 256

// dynamic smem layout (bytes)
#define OFF_PIJ   0
#define OFF_EMB   1504                          // 1482 rounded to 16B
#define EMB_BYTES (F * ESTR * 4)                // 3120 per warp
#define OFF_SCORE (OFF_EMB + WARPS * EMB_BYTES) // 1504 + 24960 = 26464
#define SCORE_BYTES (NPAIR * 4)                 // 2964 per warp
#define SMEM_TOTAL (OFF_SCORE + WARPS * SCORE_BYTES)  // 50176 B

// MLP constants: warp-uniform, compile-time offsets -> uniform const-port
__constant__ __align__(16) float c_W[E * A];
__constant__ __align__(16) float c_ab[A];
__constant__ __align__(16) float c_h[A];
__constant__ __align__(16) float c_pp[E];

// packed fp32x2 FMA (sm_100+; ptxas only emits FFMA2 via this PTX form)
#define FMA2(d, a, b, c) \
    asm("fma.rn.f32x2 %0, %1, %2, %3;" : "=l"(d) : "l"(a), "l"(b), "l"(c))

__global__ __launch_bounds__(THREADS, 3) void afm_kernel(
    const int*   __restrict__ feat_index,   // [B,F]
    const float* __restrict__ feat_value,   // [B,F]
    const float* __restrict__ fow,          // [V,1]
    const float* __restrict__ emb_table,    // [V,E]
    const float* __restrict__ bias,         // [1]
    float*       __restrict__ out,          // [B]
    int nb)
{
    extern __shared__ __align__(16) char dynsmem[];
    unsigned short* s_pij = (unsigned short*)(dynsmem + OFF_PIJ);

    const int tid  = threadIdx.x;
    const int lane = tid & 31;
    const int wid  = tid >> 5;

    // ---- one-time CTA-wide pair table (row-independent) ----
    for (int p = tid; p < NPAIR; p += THREADS) {
        int i = (int)floorf((77.0f - sqrtf(5929.0f - 8.0f * (float)p)) * 0.5f);
        if (i < 0) i = 0;
        if (i > F - 2) i = F - 2;
        while (i < F - 2 && (77 * (i + 1) - (i + 1) * (i + 1)) / 2 <= p) ++i;
        while (i > 0 && (77 * i - i * i) / 2 > p) --i;
        int j = i + 1 + (p - (77 * i - i * i) / 2);
        s_pij[p] = (unsigned short)(i | (j << 8));
    }
    __syncthreads();   // the ONLY block-wide barrier

    const int row = blockIdx.x * WARPS + wid;
    if (row >= nb) return;

    float* emb   = (float*)(dynsmem + OFF_EMB   + wid * EMB_BYTES);
    float* score = (float*)(dynsmem + OFF_SCORE + wid * SCORE_BYTES);
    // temp aliases inside this warp's score region (dead before scores are written)
    int*   t_idx = (int*)score;          // [0,39)
    float* t_val = score + 64;           // [64,103)

    // ---- Phase A: indices, values, first-order, gather ----
    t_idx[lane] = feat_index[row * F + lane];
    t_val[lane] = feat_value[row * F + lane];
    if (lane < F - 32) {
        t_idx[32 + lane] = feat_index[row * F + 32 + lane];
        t_val[32 + lane] = feat_value[row * F + 32 + lane];
    }
    __syncwarp();

    float fo = t_val[lane] * fow[t_idx[lane]];
    if (lane < F - 32) fo += t_val[32 + lane] * fow[t_idx[32 + lane]];

    for (int t = lane; t < F * E; t += 32) {
        int f = t >> 4, e = t & 15;
        emb[f * ESTR + e] = emb_table[t_idx[f] * E + e] * t_val[f];
    }
    __syncwarp();   // all temp reads done; emb visible

    #pragma unroll
    for (int o = 16; o > 0; o >>= 1) fo += __shfl_xor_sync(~0u, fo, o);

    // ---- Phase B: pair scores (float4 emb loads, LDCU.128 W, packed MLP) ----
    float mloc = -1e30f;
    #pragma unroll 1
    for (int it = 0; it < 24; ++it) {
        int  p   = it * 32 + lane;
        bool act = p < NPAIR;
        int  v   = s_pij[act ? p : 0];
        const float4* ei4 = (const float4*)(emb + (v & 255) * ESTR);
        const float4* ej4 = (const float4*)(emb + (v >> 8) * ESTR);

        unsigned long long att[8];
        #pragma unroll
        for (int k = 0; k < 8; ++k)
            att[k] = ((const unsigned long long*)c_ab)[k];

        #pragma unroll
        for (int q = 0; q < 4; ++q) {
            float4 va = ei4[q];
            float4 vb = ej4[q];
            float bes[4];
            bes[0] = va.x * vb.x;
            bes[1] = va.y * vb.y;
            bes[2] = va.z * vb.z;
            bes[3] = va.w * vb.w;
            #pragma unroll
            for (int s = 0; s < 4; ++s) {
                const int e = 4 * q + s;
                unsigned long long be2;
                asm("mov.b64 %0, {%1, %1};" : "=l"(be2) : "f"(bes[s]));
                const ulonglong2* w = (const ulonglong2*)(c_W + e * A);
                ulonglong2 w01 = w[0], w23 = w[1], w45 = w[2], w67 = w[3];
                FMA2(att[0], be2, w01.x, att[0]);
                FMA2(att[1], be2, w01.y, att[1]);
                FMA2(att[2], be2, w23.x, att[2]);
                FMA2(att[3], be2, w23.y, att[3]);
                FMA2(att[4], be2, w45.x, att[4]);
                FMA2(att[5], be2, w45.y, att[5]);
                FMA2(att[6], be2, w67.x, att[6]);
                FMA2(att[7], be2, w67.y, att[7]);
            }
        }

        float sc = 0.0f;
        #pragma unroll
        for (int k = 0; k < 8; ++k) {
            float lo, hi;
            asm("mov.b64 {%0, %1}, %2;" : "=f"(lo), "=f"(hi) : "l"(att[k]));
            sc = fmaf(fmaxf(lo, 0.0f), c_h[2 * k],     sc);
            sc = fmaf(fmaxf(hi, 0.0f), c_h[2 * k + 1], sc);
        }
        if (act) { score[p] = sc; mloc = fmaxf(mloc, sc); }
    }

    // ---- Phase C: warp softmax over 741 pairs ----
    #pragma unroll
    for (int o = 16; o > 0; o >>= 1) mloc = fmaxf(mloc, __shfl_xor_sync(~0u, mloc, o));

    float z = 0.0f;
    #pragma unroll 1
    for (int it = 0; it < 24; ++it) {
        int p = it * 32 + lane;
        if (p < NPAIR) {
            float ev = __expf(score[p] - mloc);
            score[p] = ev;
            z += ev;
        }
    }
    __syncwarp();
    #pragma unroll
    for (int o = 16; o > 0; o >>= 1) z += __shfl_xor_sync(~0u, z, o);

    // ---- Phase D: weighted pooled sum, projection, sigmoid ----
    {
        const int e = lane & 15;
        const int g = lane >> 4;     // 2 pair-groups
        float acc = 0.0f;
        #pragma unroll 2
        for (int p = g; p < NPAIR; p += 2) {
            int v = s_pij[p];
            acc = fmaf(score[p],
                       emb[(v & 255) * ESTR + e] * emb[(v >> 8) * ESTR + e],
                       acc);
        }
        acc += __shfl_xor_sync(~0u, acc, 16);
        float aw = acc * c_pp[e];
        #pragma unroll
        for (int o = 8; o > 0; o >>= 1) aw += __shfl_xor_sync(~0u, aw, o);

        if (lane == 0) {
            float y = bias[0] + fo + aw / z;
            out[row] = 1.0f / (1.0f + __expf(-y));
        }
    }
}

extern "C" void kernel_launch(void* const* d_in, const int* in_sizes, int n_in,
                              void* d_out, int out_size) {
    const int*   feat_index = (const int*)  d_in[0];
    const float* feat_value = (const float*)d_in[1];
    const float* fow        = (const float*)d_in[2];
    const float* emb_table  = (const float*)d_in[3];
    const float* bias       = (const float*)d_in[4];
    float* out = (float*)d_out;

    // Stage the tiny MLP weights into constant memory (graph-capturable
    // device-to-device async copies; no allocation).
    cudaMemcpyToSymbolAsync(c_W,  d_in[5], E * A * sizeof(float), 0, cudaMemcpyDeviceToDevice);
    cudaMemcpyToSymbolAsync(c_ab, d_in[6], A * sizeof(float),     0, cudaMemcpyDeviceToDevice);
    cudaMemcpyToSymbolAsync(c_h,  d_in[7], A * sizeof(float),     0, cudaMemcpyDeviceToDevice);
    cudaMemcpyToSymbolAsync(c_pp, d_in[8], E * sizeof(float),     0, cudaMemcpyDeviceToDevice);

    // Opt in to >48KB dynamic smem (host-side attribute; capture-safe, no alloc).
    cudaFuncSetAttribute(afm_kernel, cudaFuncAttributeMaxDynamicSharedMemorySize,
                         SMEM_TOTAL);

    int nb = in_sizes[0] / F;   // batch rows
    int blocks = (nb + WARPS - 1) / WARPS;
    afm_kernel<<<blocks, THREADS, SMEM_TOTAL>>>(feat_index, feat_value, fow,
                                                emb_table, bias, out, nb);
}